// round 5
// baseline (speedup 1.0000x reference)
#include <cuda_runtime.h>
#include <cuda_bf16.h>
#include <math.h>
#include <stdint.h>

#define B_ 8
#define T_ 64
#define N_ 256
#define H_ 8
#define D_ 64
#define FEAT 512
#define TOKENS (B_*T_*N_)          /* 131072 */
#define ELEMS  (TOKENS*FEAT)       /* 67108864 */
#define WSZ    (512*512)

// ---------------------------------------------------------------------------
// Scratch (device globals — no cudaMalloc allowed)
// ---------------------------------------------------------------------------
__device__ float g_s0[ELEMS];
__device__ float g_s2[ELEMS];
__device__ float g_s3[ELEMS];
__device__ float g_s4[ELEMS];
__device__ __nv_bfloat16 g_bf[10ull * ELEMS];
__device__ __nv_bfloat16 g_wh[6 * WSZ];
__device__ __nv_bfloat16 g_wl[6 * WSZ];

// ---------------------------------------------------------------------------
// Helpers
// ---------------------------------------------------------------------------
__device__ __forceinline__ uint32_t smem_u32(const void* p) {
    uint32_t a;
    asm("{ .reg .u64 t; cvta.to.shared.u64 t, %1; cvt.u32.u64 %0, t; }" : "=r"(a) : "l"(p));
    return a;
}

__device__ __forceinline__ void cp16(uint32_t dst, const void* src) {
    asm volatile("cp.async.cg.shared.global [%0], [%1], 16;"
                 :: "r"(dst), "l"(__cvta_generic_to_global(src)));
}

__device__ __forceinline__ void ldsm4(uint32_t addr, uint32_t* r) {
    asm volatile("ldmatrix.sync.aligned.m8n8.x4.shared.b16 {%0,%1,%2,%3}, [%4];"
                 : "=r"(r[0]), "=r"(r[1]), "=r"(r[2]), "=r"(r[3]) : "r"(addr));
}

__device__ __forceinline__ void mma_bf16(float* d, const uint32_t* a,
                                         uint32_t b0, uint32_t b1) {
    asm volatile(
        "mma.sync.aligned.m16n8k16.row.col.f32.bf16.bf16.f32 "
        "{%0,%1,%2,%3}, {%4,%5,%6,%7}, {%8,%9}, {%0,%1,%2,%3};"
        : "+f"(d[0]), "+f"(d[1]), "+f"(d[2]), "+f"(d[3])
        : "r"(a[0]), "r"(a[1]), "r"(a[2]), "r"(a[3]), "r"(b0), "r"(b1));
}

__device__ __forceinline__ void split2(float x, float y,
                                       __nv_bfloat162& h, __nv_bfloat162& l) {
    h = __floats2bfloat162_rn(x, y);
    l = __floats2bfloat162_rn(x - __low2float(h), y - __high2float(h));
}

// ---------------------------------------------------------------------------
// Weight prep: transpose + hi/lo split. Wh/Wl[z][n][k] = split(W_z[k][n]).
// ---------------------------------------------------------------------------
__global__ __launch_bounds__(256)
void prep_w(const float* W0, const float* W1, const float* W2,
            const float* W3, const float* W4, const float* W5,
            __nv_bfloat16* __restrict__ Wh, __nv_bfloat16* __restrict__ Wl)
{
    const float* Ws[6] = {W0, W1, W2, W3, W4, W5};
    const float* W = Ws[blockIdx.z];
    __shared__ float t[32][33];
    int bx = blockIdx.x * 32, by = blockIdx.y * 32;
#pragma unroll
    for (int r = 0; r < 32; r += 8)
        t[threadIdx.y + r][threadIdx.x] =
            W[(size_t)(by + threadIdx.y + r) * 512 + bx + threadIdx.x];
    __syncthreads();
    size_t base = (size_t)blockIdx.z * WSZ;
#pragma unroll
    for (int r = 0; r < 32; r += 8) {
        float v = t[threadIdx.x][threadIdx.y + r];
        __nv_bfloat16 h = __float2bfloat16_rn(v);
        size_t o = base + (size_t)(bx + threadIdx.y + r) * 512 + by + threadIdx.x;
        Wh[o] = h;
        Wl[o] = __float2bfloat16_rn(v - __bfloat162float(h));
    }
}

// ---------------------------------------------------------------------------
// Fused residual adds: s0 = xl+te (fp32 + split), split(xh+te).
// ---------------------------------------------------------------------------
__global__ __launch_bounds__(256)
void add_te01(const float4* __restrict__ xl, const float4* __restrict__ xh,
              const float4* __restrict__ te, float4* __restrict__ s0,
              __nv_bfloat162* __restrict__ h0o, __nv_bfloat162* __restrict__ l0o,
              __nv_bfloat162* __restrict__ h1o, __nv_bfloat162* __restrict__ l1o)
{
    int i = blockIdx.x * 256 + threadIdx.x;
    float4 t = te[i];
    float4 a = xl[i];
    float4 b = xh[i];
    float4 r0 = make_float4(a.x + t.x, a.y + t.y, a.z + t.z, a.w + t.w);
    float4 r1 = make_float4(b.x + t.x, b.y + t.y, b.z + t.z, b.w + t.w);
    s0[i] = r0;
    __nv_bfloat162 h0, l0, h1, l1;
    split2(r0.x, r0.y, h0, l0);
    split2(r0.z, r0.w, h1, l1);
    h0o[2 * i] = h0; h0o[2 * i + 1] = h1;
    l0o[2 * i] = l0; l0o[2 * i + 1] = l1;
    split2(r1.x, r1.y, h0, l0);
    split2(r1.z, r1.w, h1, l1);
    h1o[2 * i] = h0; h1o[2 * i + 1] = h1;
    l1o[2 * i] = l0; l1o[2 * i + 1] = l1;
}

// ---------------------------------------------------------------------------
// 3xBF16 tensor-core GEMM, cp.async 3-stage pipeline, pre-split bf16 inputs.
// CTA 128x128, 128 thr, 4 warps (64x64). K chunks of 32, stages = 32KB.
// ---------------------------------------------------------------------------
#define STAGE 32768u
__global__ __launch_bounds__(128, 2)
void gemm_bf3(const __nv_bfloat16* __restrict__ Ah, const __nv_bfloat16* __restrict__ Al,
              const __nv_bfloat16* __restrict__ Bh, const __nv_bfloat16* __restrict__ Bl,
              const float* __restrict__ bias,
              float* __restrict__ Cf,
              __nv_bfloat16* __restrict__ Ch, __nv_bfloat16* __restrict__ Cl,
              int relu)
{
    extern __shared__ __align__(128) unsigned char smem[];
    const uint32_t sb = smem_u32(smem);

    const int tid  = threadIdx.x;
    const int lane = tid & 31;
    const int warp = tid >> 5;
    const int wm = warp >> 1, wn = warp & 1;
    const int m0 = blockIdx.y * 128;
    const int n0 = blockIdx.x * 128;

    const __nv_bfloat16* Ahg = Ah + (size_t)m0 * 512;
    const __nv_bfloat16* Alg = Al + (size_t)m0 * 512;
    const __nv_bfloat16* Bhg = Bh + (size_t)n0 * 512;
    const __nv_bfloat16* Blg = Bl + (size_t)n0 * 512;

    int frow[4], fc[4];
    uint32_t foff[4];
#pragma unroll
    for (int j = 0; j < 4; j++) {
        int lin = tid + j * 128;
        frow[j] = lin >> 2;
        fc[j]   = lin & 3;
        foff[j] = frow[j] * 64 + ((uint32_t)(fc[j] ^ ((frow[j] >> 1) & 3)) << 4);
    }

#define FILL(kc, stg)                                                         \
    do {                                                                      \
        uint32_t s_ = sb + (stg) * STAGE;                                     \
        _Pragma("unroll")                                                     \
        for (int j = 0; j < 4; j++) {                                         \
            size_t g_ = (size_t)frow[j] * 512 + (kc) * 32 + fc[j] * 8;        \
            cp16(s_ + foff[j],          Ahg + g_);                            \
            cp16(s_ + 8192  + foff[j],  Alg + g_);                            \
            cp16(s_ + 16384 + foff[j],  Bhg + g_);                            \
            cp16(s_ + 24576 + foff[j],  Blg + g_);                            \
        }                                                                     \
        asm volatile("cp.async.commit_group;");                               \
    } while (0)

    float acc[4][8][4];
#pragma unroll
    for (int i = 0; i < 4; i++)
#pragma unroll
        for (int j = 0; j < 8; j++)
#pragma unroll
            for (int k = 0; k < 4; k++) acc[i][j][k] = 0.f;

    const int rA_base = wm * 64 + (lane & 7) + ((lane >> 3) & 1) * 8;
    const uint32_t kbA = ((lane >> 4) & 1) * 16;
    const int rB_base = wn * 64 + (lane & 7) + ((lane >> 4) & 1) * 8;
    const uint32_t kbB = ((lane >> 3) & 1) * 16;

    FILL(0, 0);
    FILL(1, 1);
    FILL(2, 2);

    int stg = 0;
    for (int c = 0; c < 16; c++) {
        if (c <= 13)      asm volatile("cp.async.wait_group 2;");
        else if (c == 14) asm volatile("cp.async.wait_group 1;");
        else              asm volatile("cp.async.wait_group 0;");
        __syncthreads();

        const uint32_t sAh = sb + stg * STAGE, sAl = sAh + 8192;
        const uint32_t sBh = sAh + 16384, sBl = sAh + 24576;

#pragma unroll
        for (int ks = 0; ks < 2; ks++) {
            uint32_t ah[4][4], al[4][4];
#pragma unroll
            for (int mt = 0; mt < 4; mt++) {
                int r = rA_base + mt * 16;
                uint32_t kb = kbA + ks * 32;
                uint32_t off = r * 64 + (kb ^ (((r >> 1) & 3) << 4));
                ldsm4(sAh + off, ah[mt]);
                ldsm4(sAl + off, al[mt]);
            }
#pragma unroll
            for (int p = 0; p < 4; p++) {
                uint32_t bh[4], bl[4];
                int r = rB_base + p * 16;
                uint32_t kb = kbB + ks * 32;
                uint32_t off = r * 64 + (kb ^ (((r >> 1) & 3) << 4));
                ldsm4(sBh + off, bh);
                ldsm4(sBl + off, bl);
#pragma unroll
                for (int mt = 0; mt < 4; mt++) {
                    mma_bf16(acc[mt][2 * p],     ah[mt], bh[0], bh[1]);
                    mma_bf16(acc[mt][2 * p],     ah[mt], bl[0], bl[1]);
                    mma_bf16(acc[mt][2 * p],     al[mt], bh[0], bh[1]);
                    mma_bf16(acc[mt][2 * p + 1], ah[mt], bh[2], bh[3]);
                    mma_bf16(acc[mt][2 * p + 1], ah[mt], bl[2], bl[3]);
                    mma_bf16(acc[mt][2 * p + 1], al[mt], bh[2], bh[3]);
                }
            }
        }
        __syncthreads();
        if (c + 3 < 16) FILL(c + 3, stg);
        stg = (stg == 2) ? 0 : stg + 1;
    }

    // ---- epilogue ----
#pragma unroll
    for (int mt = 0; mt < 4; mt++) {
        int row = m0 + wm * 64 + mt * 16 + (lane >> 2);
#pragma unroll
        for (int nt = 0; nt < 8; nt++) {
            int col = n0 + wn * 64 + nt * 8 + (lane & 3) * 2;
            float2 bb = __ldg((const float2*)(bias + col));
            float v0 = acc[mt][nt][0] + bb.x;
            float v1 = acc[mt][nt][1] + bb.y;
            float v2 = acc[mt][nt][2] + bb.x;
            float v3 = acc[mt][nt][3] + bb.y;
            if (relu) {
                v0 = fmaxf(v0, 0.f); v1 = fmaxf(v1, 0.f);
                v2 = fmaxf(v2, 0.f); v3 = fmaxf(v3, 0.f);
            }
            if (Cf) {
                *(float2*)(Cf + (size_t)row * 512 + col)       = make_float2(v0, v1);
                *(float2*)(Cf + (size_t)(row + 8) * 512 + col) = make_float2(v2, v3);
            }
            if (Ch) {
                __nv_bfloat162 h0, l0, h1, l1;
                split2(v0, v1, h0, l0);
                split2(v2, v3, h1, l1);
                *(__nv_bfloat162*)(Ch + (size_t)row * 512 + col)       = h0;
                *(__nv_bfloat162*)(Cl + (size_t)row * 512 + col)       = l0;
                *(__nv_bfloat162*)(Ch + (size_t)(row + 8) * 512 + col) = h1;
                *(__nv_bfloat162*)(Cl + (size_t)(row + 8) * 512 + col) = l1;
            }
        }
    }
#undef FILL
}

// ---------------------------------------------------------------------------
// Causal attention per (b, n, h): T=64, D=64. Pad-68 K rows: conflict-free
// LDS.128 in QK loop. Masked BEFORE scaling: masked logit = -32767/8.
// Dynamic smem: Qs 16KB | Ks 64x68 f32 (17408B) | Vs 16KB = 49792B.
// ---------------------------------------------------------------------------
__global__ __launch_bounds__(256)
void attn64(const float* __restrict__ q, const float* __restrict__ k,
            const float* __restrict__ v,
            __nv_bfloat16* __restrict__ oh, __nv_bfloat16* __restrict__ ol)
{
    extern __shared__ __align__(16) float dsm[];
    float* Qs = dsm;              // [64][64]
    float* Ks = dsm + 4096;       // [64][68]
    float* Vs = dsm + 4096 + 64 * 68;  // [64][64]

    const int idx = blockIdx.x;
    const int h = idx & 7;
    const int n = (idx >> 3) & 255;
    const int b = idx >> 11;
    const size_t base = ((size_t)(b * T_) * N_ + n) * FEAT + h * D_;
    const int tid = threadIdx.x;
    const size_t tstride = (size_t)N_ * FEAT;

    for (int i = tid; i < 4096; i += 256) {
        int t = i >> 6, d = i & 63;
        size_t off = base + (size_t)t * tstride + d;
        Qs[i] = q[off];
        Ks[t * 68 + d] = k[off];
        Vs[i] = v[off];
    }
    __syncthreads();

    const int w = tid >> 5;
    const int l = tid & 31;
    const float NEG8 = -4095.875f;
    const float* K0 = Ks + l * 68;
    const float* K1 = Ks + (l + 32) * 68;

#pragma unroll
    for (int r = 0; r < 8; r++) {
        int t = w * 8 + r;
        const float* qrow = Qs + t * 64;
        float s0 = 0.f, s1 = 0.f;
#pragma unroll
        for (int d = 0; d < 64; d += 4) {
            float4 q4 = *(const float4*)(qrow + d);
            float4 k0 = *(const float4*)(K0 + d);
            float4 k1 = *(const float4*)(K1 + d);
            s0 += q4.x * k0.x + q4.y * k0.y + q4.z * k0.z + q4.w * k0.w;
            s1 += q4.x * k1.x + q4.y * k1.y + q4.z * k1.z + q4.w * k1.w;
        }
        float l0 = (l      <= t) ? s0 * 0.125f : NEG8;
        float l1 = (l + 32 <= t) ? s1 * 0.125f : NEG8;
        float m = fmaxf(l0, l1);
#pragma unroll
        for (int o = 16; o; o >>= 1) m = fmaxf(m, __shfl_xor_sync(0xffffffffu, m, o));
        float e0 = __expf(l0 - m), e1 = __expf(l1 - m);
        float sum = e0 + e1;
#pragma unroll
        for (int o = 16; o; o >>= 1) sum += __shfl_xor_sync(0xffffffffu, sum, o);
        float inv = 1.f / sum;
        float p0 = e0 * inv, p1 = e1 * inv;

        float a0 = 0.f, a1 = 0.f;
#pragma unroll
        for (int s = 0; s < 32; s++) {
            float ps = __shfl_sync(0xffffffffu, p0, s);
            a0 += ps * Vs[s * 64 + l];
            a1 += ps * Vs[s * 64 + l + 32];
        }
#pragma unroll
        for (int s = 0; s < 32; s++) {
            float ps = __shfl_sync(0xffffffffu, p1, s);
            a0 += ps * Vs[(s + 32) * 64 + l];
            a1 += ps * Vs[(s + 32) * 64 + l + 32];
        }
        size_t ooff = base + (size_t)t * tstride;
        __nv_bfloat16 h0 = __float2bfloat16_rn(a0);
        __nv_bfloat16 h1 = __float2bfloat16_rn(a1);
        oh[ooff + l]      = h0;
        oh[ooff + l + 32] = h1;
        ol[ooff + l]      = __float2bfloat16_rn(a0 - __bfloat162float(h0));
        ol[ooff + l + 32] = __float2bfloat16_rn(a1 - __bfloat162float(h1));
    }
}

// ---------------------------------------------------------------------------
// out = LayerNorm(a + b); optional bf16 hi/lo split. One warp per row.
// ---------------------------------------------------------------------------
__global__ __launch_bounds__(256)
void add_ln(const float* __restrict__ a, const float* __restrict__ b,
            float* __restrict__ out,
            __nv_bfloat162* __restrict__ oh, __nv_bfloat162* __restrict__ ol)
{
    int row = blockIdx.x * 8 + (threadIdx.x >> 5);
    int l = threadIdx.x & 31;
    const float4* pa = (const float4*)(a + (size_t)row * 512);
    const float4* pb = (const float4*)(b + (size_t)row * 512);

    float4 x[4];
    float s = 0.f;
#pragma unroll
    for (int i = 0; i < 4; i++) {
        float4 u = pa[l + i * 32], w = pb[l + i * 32];
        x[i] = make_float4(u.x + w.x, u.y + w.y, u.z + w.z, u.w + w.w);
        s += x[i].x + x[i].y + x[i].z + x[i].w;
    }
#pragma unroll
    for (int o = 16; o; o >>= 1) s += __shfl_xor_sync(0xffffffffu, s, o);
    float mean = s * (1.f / 512.f);

    float vs = 0.f;
#pragma unroll
    for (int i = 0; i < 4; i++) {
        float dx = x[i].x - mean, dy = x[i].y - mean, dz = x[i].z - mean, dw = x[i].w - mean;
        vs += dx * dx + dy * dy + dz * dz + dw * dw;
    }
#pragma unroll
    for (int o = 16; o; o >>= 1) vs += __shfl_xor_sync(0xffffffffu, vs, o);
    float invstd = rsqrtf(vs * (1.f / 512.f) + 1e-5f);

    float4* po = (float4*)(out + (size_t)row * 512);
#pragma unroll
    for (int i = 0; i < 4; i++) {
        float y0 = (x[i].x - mean) * invstd, y1 = (x[i].y - mean) * invstd;
        float y2 = (x[i].z - mean) * invstd, y3 = (x[i].w - mean) * invstd;
        int fi = row * 128 + l + i * 32;
        po[l + i * 32] = make_float4(y0, y1, y2, y3);
        if (oh) {
            __nv_bfloat162 h0, l0, h1, l1;
            split2(y0, y1, h0, l0);
            split2(y2, y3, h1, l1);
            oh[2 * fi] = h0; oh[2 * fi + 1] = h1;
            ol[2 * fi] = l0; ol[2 * fi + 1] = l1;
        }
    }
}

// ---------------------------------------------------------------------------
// Launch pipeline (graph-capturable: launches only)
// ---------------------------------------------------------------------------
extern "C" void kernel_launch(void* const* d_in, const int* in_sizes, int n_in,
                              void* d_out, int out_size)
{
    const float* xl = (const float*)d_in[0];
    const float* xh = (const float*)d_in[1];
    const float* te = (const float*)d_in[2];
    const float* Wq = (const float*)d_in[3];
    const float* bq = (const float*)d_in[4];
    const float* Wk = (const float*)d_in[5];
    const float* bk = (const float*)d_in[6];
    const float* Wv = (const float*)d_in[7];
    const float* bv = (const float*)d_in[8];
    const float* Wo = (const float*)d_in[9];
    const float* bo = (const float*)d_in[10];
    const float* W1 = (const float*)d_in[11];
    const float* b1 = (const float*)d_in[12];
    const float* W2 = (const float*)d_in[13];
    const float* b2 = (const float*)d_in[14];
    float* out = (float*)d_out;

    float *s0, *s2, *s3, *s4;
    __nv_bfloat16 *bf, *wh, *wl;
    cudaGetSymbolAddress((void**)&s0, g_s0);
    cudaGetSymbolAddress((void**)&s2, g_s2);
    cudaGetSymbolAddress((void**)&s3, g_s3);
    cudaGetSymbolAddress((void**)&s4, g_s4);
    cudaGetSymbolAddress((void**)&bf, g_bf);
    cudaGetSymbolAddress((void**)&wh, g_wh);
    cudaGetSymbolAddress((void**)&wl, g_wl);

    __nv_bfloat16* s0h = bf + 0ull * ELEMS;
    __nv_bfloat16* s0l = bf + 1ull * ELEMS;
    __nv_bfloat16* s1h = bf + 2ull * ELEMS;
    __nv_bfloat16* s1l = bf + 3ull * ELEMS;
    __nv_bfloat16* aoh = bf + 4ull * ELEMS;
    __nv_bfloat16* aol = bf + 5ull * ELEMS;
    __nv_bfloat16* vh  = bf + 6ull * ELEMS;
    __nv_bfloat16* vl  = bf + 7ull * ELEMS;
    __nv_bfloat16* f1h = bf + 8ull * ELEMS;
    __nv_bfloat16* f1l = bf + 9ull * ELEMS;

    cudaFuncSetAttribute(gemm_bf3, cudaFuncAttributeMaxDynamicSharedMemorySize, 3 * 32768);
    cudaFuncSetAttribute(attn64, cudaFuncAttributeMaxDynamicSharedMemorySize, 50176);

    const dim3 gg(4, 1024);            // N/128 x M/128
    const int nadd = ELEMS / 4 / 256;
    const int ATTN_SMEM = (4096 + 64 * 68 + 4096) * 4;

    // 0: weights transpose + split
    prep_w<<<dim3(16, 16, 6), dim3(32, 8)>>>(Wq, Wk, Wv, Wo, W1, W2, wh, wl);
    // 1: fused residual adds + splits
    add_te01<<<nadd, 256>>>((const float4*)xl, (const float4*)xh, (const float4*)te,
                            (float4*)s0,
                            (__nv_bfloat162*)s0h, (__nv_bfloat162*)s0l,
                            (__nv_bfloat162*)s1h, (__nv_bfloat162*)s1l);
    // 2,3,4: Q, K, V projections
    gemm_bf3<<<gg, 128, 3 * 32768>>>(s0h, s0l, wh + 0 * WSZ, wl + 0 * WSZ, bq, s2, 0, 0, 0);
    gemm_bf3<<<gg, 128, 3 * 32768>>>(s1h, s1l, wh + 1 * WSZ, wl + 1 * WSZ, bk, s3, 0, 0, 1);
    gemm_bf3<<<gg, 128, 3 * 32768>>>(s1h, s1l, wh + 2 * WSZ, wl + 2 * WSZ, bv, s4, 0, 0, 1);
    // 5: attention (ncu -s 5 target)
    attn64<<<B_ * N_ * H_, 256, ATTN_SMEM>>>(s2, s3, s4, aoh, aol);
    // 6: Wo projection
    gemm_bf3<<<gg, 128, 3 * 32768>>>(aoh, aol, wh + 3 * WSZ, wl + 3 * WSZ, bo, s3, 0, 0, 0);
    // 7: val = LN(o + s0)
    add_ln<<<TOKENS / 8, 256>>>(s3, s0, s4, (__nv_bfloat162*)vh, (__nv_bfloat162*)vl);
    // 8: ff1 = relu(val @ W1 + b1)
    gemm_bf3<<<gg, 128, 3 * 32768>>>(vh, vl, wh + 4 * WSZ, wl + 4 * WSZ, b1, 0, f1h, f1l, 1);
    // 9: ff2 = ff1 @ W2 + b2
    gemm_bf3<<<gg, 128, 3 * 32768>>>(f1h, f1l, wh + 5 * WSZ, wl + 5 * WSZ, b2, s0, 0, 0, 0);
    // 10: out = LN(ff2 + val)
    add_ln<<<TOKENS / 8, 256>>>(s0, s4, out, 0, 0);
}

// round 6
// speedup vs baseline: 1.4153x; 1.4153x over previous
#include <cuda_runtime.h>
#include <cuda_bf16.h>
#include <math.h>
#include <stdint.h>

#define B_ 8
#define T_ 64
#define N_ 256
#define H_ 8
#define D_ 64
#define FEAT 512
#define TOKENS (B_*T_*N_)          /* 131072 */
#define ELEMS  (TOKENS*FEAT)       /* 67108864 */
#define WSZ    (512*512)

// ---------------------------------------------------------------------------
// Scratch (device globals — no cudaMalloc allowed)
// ---------------------------------------------------------------------------
__device__ float g_s0[ELEMS];
__device__ float g_s2[ELEMS];
__device__ float g_s3[ELEMS];
__device__ float g_s4[ELEMS];
__device__ __nv_bfloat16 g_bf[10ull * ELEMS];
__device__ __nv_bfloat16 g_wh[6 * WSZ];
__device__ __nv_bfloat16 g_wl[6 * WSZ];

// ---------------------------------------------------------------------------
// Helpers
// ---------------------------------------------------------------------------
__device__ __forceinline__ uint32_t smem_u32(const void* p) {
    uint32_t a;
    asm("{ .reg .u64 t; cvta.to.shared.u64 t, %1; cvt.u32.u64 %0, t; }" : "=r"(a) : "l"(p));
    return a;
}

__device__ __forceinline__ void cp16(uint32_t dst, const void* src) {
    asm volatile("cp.async.cg.shared.global [%0], [%1], 16;"
                 :: "r"(dst), "l"(__cvta_generic_to_global(src)));
}

__device__ __forceinline__ void ldsm4(uint32_t addr, uint32_t* r) {
    asm volatile("ldmatrix.sync.aligned.m8n8.x4.shared.b16 {%0,%1,%2,%3}, [%4];"
                 : "=r"(r[0]), "=r"(r[1]), "=r"(r[2]), "=r"(r[3]) : "r"(addr));
}

__device__ __forceinline__ void mma_bf16(float* d, const uint32_t* a,
                                         uint32_t b0, uint32_t b1) {
    asm volatile(
        "mma.sync.aligned.m16n8k16.row.col.f32.bf16.bf16.f32 "
        "{%0,%1,%2,%3}, {%4,%5,%6,%7}, {%8,%9}, {%0,%1,%2,%3};"
        : "+f"(d[0]), "+f"(d[1]), "+f"(d[2]), "+f"(d[3])
        : "r"(a[0]), "r"(a[1]), "r"(a[2]), "r"(a[3]), "r"(b0), "r"(b1));
}

__device__ __forceinline__ void split2(float x, float y,
                                       __nv_bfloat162& h, __nv_bfloat162& l) {
    h = __floats2bfloat162_rn(x, y);
    l = __floats2bfloat162_rn(x - __low2float(h), y - __high2float(h));
}

// ---------------------------------------------------------------------------
// Weight prep: transpose + hi/lo split. Wh/Wl[z][n][k] = split(W_z[k][n]).
// ---------------------------------------------------------------------------
__global__ __launch_bounds__(256)
void prep_w(const float* W0, const float* W1, const float* W2,
            const float* W3, const float* W4, const float* W5,
            __nv_bfloat16* __restrict__ Wh, __nv_bfloat16* __restrict__ Wl)
{
    const float* Ws[6] = {W0, W1, W2, W3, W4, W5};
    const float* W = Ws[blockIdx.z];
    __shared__ float t[32][33];
    int bx = blockIdx.x * 32, by = blockIdx.y * 32;
#pragma unroll
    for (int r = 0; r < 32; r += 8)
        t[threadIdx.y + r][threadIdx.x] =
            W[(size_t)(by + threadIdx.y + r) * 512 + bx + threadIdx.x];
    __syncthreads();
    size_t base = (size_t)blockIdx.z * WSZ;
#pragma unroll
    for (int r = 0; r < 32; r += 8) {
        float v = t[threadIdx.x][threadIdx.y + r];
        __nv_bfloat16 h = __float2bfloat16_rn(v);
        size_t o = base + (size_t)(bx + threadIdx.y + r) * 512 + by + threadIdx.x;
        Wh[o] = h;
        Wl[o] = __float2bfloat16_rn(v - __bfloat162float(h));
    }
}

// ---------------------------------------------------------------------------
// Fused residual adds: s0 = xl+te (fp32 + split), split(xh+te).
// ---------------------------------------------------------------------------
__global__ __launch_bounds__(256)
void add_te01(const float4* __restrict__ xl, const float4* __restrict__ xh,
              const float4* __restrict__ te, float4* __restrict__ s0,
              __nv_bfloat162* __restrict__ h0o, __nv_bfloat162* __restrict__ l0o,
              __nv_bfloat162* __restrict__ h1o, __nv_bfloat162* __restrict__ l1o)
{
    int i = blockIdx.x * 256 + threadIdx.x;
    float4 t = te[i];
    float4 a = xl[i];
    float4 b = xh[i];
    float4 r0 = make_float4(a.x + t.x, a.y + t.y, a.z + t.z, a.w + t.w);
    float4 r1 = make_float4(b.x + t.x, b.y + t.y, b.z + t.z, b.w + t.w);
    s0[i] = r0;
    __nv_bfloat162 h0, l0, h1, l1;
    split2(r0.x, r0.y, h0, l0);
    split2(r0.z, r0.w, h1, l1);
    h0o[2 * i] = h0; h0o[2 * i + 1] = h1;
    l0o[2 * i] = l0; l0o[2 * i + 1] = l1;
    split2(r1.x, r1.y, h0, l0);
    split2(r1.z, r1.w, h1, l1);
    h1o[2 * i] = h0; h1o[2 * i + 1] = h1;
    l1o[2 * i] = l0; l1o[2 * i + 1] = l1;
}

// ---------------------------------------------------------------------------
// 3xBF16 tensor-core GEMM, 2-stage cp.async pipeline (R4 config).
// CTA 128x128, 128 thr, 4 warps (64x64). Dual-B: blocks with blockIdx.x>=4
// use the second operand set (fused K+V projection).
// ---------------------------------------------------------------------------
__global__ __launch_bounds__(128, 2)
void gemm_bf3(const __nv_bfloat16* __restrict__ Ah, const __nv_bfloat16* __restrict__ Al,
              const __nv_bfloat16* __restrict__ Bh, const __nv_bfloat16* __restrict__ Bl,
              const float* __restrict__ bias,
              float* __restrict__ Cf,
              __nv_bfloat16* __restrict__ Ch, __nv_bfloat16* __restrict__ Cl,
              int relu,
              const __nv_bfloat16* Bh2, const __nv_bfloat16* Bl2,
              const float* bias2, float* Cf2, int relu2)
{
    extern __shared__ __align__(128) unsigned char smem[];
    const uint32_t sb = smem_u32(smem);

    const int tid  = threadIdx.x;
    const int lane = tid & 31;
    const int warp = tid >> 5;
    const int wm = warp >> 1, wn = warp & 1;
    const int m0 = blockIdx.y * 128;

    int bx = blockIdx.x;
    const __nv_bfloat16* BhU = Bh;
    const __nv_bfloat16* BlU = Bl;
    const float* biasU = bias;
    float* CfU = Cf;
    int reluU = relu;
    if (bx >= 4) {
        bx -= 4;
        BhU = Bh2; BlU = Bl2; biasU = bias2; CfU = Cf2; reluU = relu2;
    }
    const int n0 = bx * 128;

    const __nv_bfloat16* Ahg = Ah  + (size_t)m0 * 512;
    const __nv_bfloat16* Alg = Al  + (size_t)m0 * 512;
    const __nv_bfloat16* Bhg = BhU + (size_t)n0 * 512;
    const __nv_bfloat16* Blg = BlU + (size_t)n0 * 512;

    int frow[4], fc[4];
    uint32_t foff[4];
#pragma unroll
    for (int j = 0; j < 4; j++) {
        int lin = tid + j * 128;
        frow[j] = lin >> 2;
        fc[j]   = lin & 3;
        foff[j] = frow[j] * 64 + ((uint32_t)(fc[j] ^ ((frow[j] >> 1) & 3)) << 4);
    }

#define FILL(kc, st)                                                          \
    do {                                                                      \
        uint32_t s_ = sb + (st) * 32768;                                      \
        _Pragma("unroll")                                                     \
        for (int j = 0; j < 4; j++) {                                         \
            size_t g_ = (size_t)frow[j] * 512 + (kc) * 32 + fc[j] * 8;        \
            cp16(s_ + foff[j],          Ahg + g_);                            \
            cp16(s_ + 8192  + foff[j],  Alg + g_);                            \
            cp16(s_ + 16384 + foff[j],  Bhg + g_);                            \
            cp16(s_ + 24576 + foff[j],  Blg + g_);                            \
        }                                                                     \
        asm volatile("cp.async.commit_group;");                               \
    } while (0)

    float acc[4][8][4];
#pragma unroll
    for (int i = 0; i < 4; i++)
#pragma unroll
        for (int j = 0; j < 8; j++)
#pragma unroll
            for (int k = 0; k < 4; k++) acc[i][j][k] = 0.f;

    const int rA_base = wm * 64 + (lane & 7) + ((lane >> 3) & 1) * 8;
    const uint32_t kbA = ((lane >> 4) & 1) * 16;
    const int rB_base = wn * 64 + (lane & 7) + ((lane >> 4) & 1) * 8;
    const uint32_t kbB = ((lane >> 3) & 1) * 16;

    FILL(0, 0);
    FILL(1, 1);

    for (int c = 0; c < 16; c++) {
        if (c < 15) asm volatile("cp.async.wait_group 1;");
        else        asm volatile("cp.async.wait_group 0;");
        __syncthreads();

        const uint32_t st = (c & 1) * 32768;
        const uint32_t sAh = sb + st, sAl = sAh + 8192;
        const uint32_t sBh = sAh + 16384, sBl = sAh + 24576;

#pragma unroll
        for (int ks = 0; ks < 2; ks++) {
            uint32_t ah[4][4], al[4][4], bh[4][4], bl[4][4];
#pragma unroll
            for (int mt = 0; mt < 4; mt++) {
                int r = rA_base + mt * 16;
                uint32_t kb = kbA + ks * 32;
                uint32_t off = r * 64 + (kb ^ (((r >> 1) & 3) << 4));
                ldsm4(sAh + off, ah[mt]);
                ldsm4(sAl + off, al[mt]);
            }
#pragma unroll
            for (int p = 0; p < 4; p++) {
                int r = rB_base + p * 16;
                uint32_t kb = kbB + ks * 32;
                uint32_t off = r * 64 + (kb ^ (((r >> 1) & 3) << 4));
                ldsm4(sBh + off, bh[p]);
                ldsm4(sBl + off, bl[p]);
            }
#pragma unroll
            for (int mt = 0; mt < 4; mt++)
#pragma unroll
                for (int nt = 0; nt < 8; nt++) {
                    int p = nt >> 1, h = (nt & 1) * 2;
                    mma_bf16(acc[mt][nt], ah[mt], bh[p][h], bh[p][h + 1]);
                    mma_bf16(acc[mt][nt], ah[mt], bl[p][h], bl[p][h + 1]);
                    mma_bf16(acc[mt][nt], al[mt], bh[p][h], bh[p][h + 1]);
                }
        }
        __syncthreads();
        if (c + 2 < 16) FILL(c + 2, (c & 1));
    }

    // ---- epilogue ----
#pragma unroll
    for (int mt = 0; mt < 4; mt++) {
        int row = m0 + wm * 64 + mt * 16 + (lane >> 2);
#pragma unroll
        for (int nt = 0; nt < 8; nt++) {
            int col = n0 + wn * 64 + nt * 8 + (lane & 3) * 2;
            float2 bb = __ldg((const float2*)(biasU + col));
            float v0 = acc[mt][nt][0] + bb.x;
            float v1 = acc[mt][nt][1] + bb.y;
            float v2 = acc[mt][nt][2] + bb.x;
            float v3 = acc[mt][nt][3] + bb.y;
            if (reluU) {
                v0 = fmaxf(v0, 0.f); v1 = fmaxf(v1, 0.f);
                v2 = fmaxf(v2, 0.f); v3 = fmaxf(v3, 0.f);
            }
            if (CfU) {
                *(float2*)(CfU + (size_t)row * 512 + col)       = make_float2(v0, v1);
                *(float2*)(CfU + (size_t)(row + 8) * 512 + col) = make_float2(v2, v3);
            }
            if (Ch) {
                __nv_bfloat162 h0, l0, h1, l1;
                split2(v0, v1, h0, l0);
                split2(v2, v3, h1, l1);
                *(__nv_bfloat162*)(Ch + (size_t)row * 512 + col)       = h0;
                *(__nv_bfloat162*)(Cl + (size_t)row * 512 + col)       = l0;
                *(__nv_bfloat162*)(Ch + (size_t)(row + 8) * 512 + col) = h1;
                *(__nv_bfloat162*)(Cl + (size_t)(row + 8) * 512 + col) = l1;
            }
        }
    }
#undef FILL
}

// ---------------------------------------------------------------------------
// Causal attention per (b, n, h): T=64, D=64. Register-blocked:
// each warp computes 8 rows; K/V chunks loaded once per warp (not per row).
// K chunk-XOR swizzled (optimal 4-phase LDS.128); V float2-interleaved;
// P tile overwrites this warp's own Q rows (warp-private -> __syncwarp only).
// Masked BEFORE scaling: masked logit = -32767/8.
// ---------------------------------------------------------------------------
__global__ __launch_bounds__(256)
void attn64(const float* __restrict__ q, const float* __restrict__ k,
            const float* __restrict__ v,
            __nv_bfloat16* __restrict__ oh, __nv_bfloat16* __restrict__ ol)
{
    __shared__ float Qs[64 * 64];   // Q, then P (per-warp rows)
    __shared__ float Ks[64 * 64];   // chunk-swizzled
    __shared__ float Vs[64 * 64];   // float2-interleaved: [s][l] = (v[s][l], v[s][l+32])

    const int idx = blockIdx.x;
    const int h = idx & 7;
    const int n = (idx >> 3) & 255;
    const int b = idx >> 11;
    const size_t base = ((size_t)(b * T_) * N_ + n) * FEAT + h * D_;
    const int tid = threadIdx.x;
    const size_t tstride = (size_t)N_ * FEAT;

    for (int i = tid; i < 4096; i += 256) {
        int t = i >> 6, d = i & 63;
        size_t off = base + (size_t)t * tstride + d;
        Qs[i] = q[off];
        Ks[t * 64 + ((((d >> 2) ^ (t & 7)) << 2) | (d & 3))] = k[off];
        Vs[t * 64 + ((d & 31) * 2 + (d >> 5))] = v[off];
    }
    __syncthreads();

    const int w = tid >> 5;
    const int l = tid & 31;
    const float NEG8 = -4095.875f;
    const float4* Kf4 = (const float4*)Ks;
    const float4* Qf4 = (const float4*)Qs;
    const int csw = l & 7;

    // ---- QK: s0[r] = q[w*8+r] . k[l], s1[r] = q[w*8+r] . k[l+32] ----
    float s0[8], s1[8];
#pragma unroll
    for (int r = 0; r < 8; r++) { s0[r] = 0.f; s1[r] = 0.f; }
#pragma unroll
    for (int c = 0; c < 16; c++) {
        float4 k0 = Kf4[l * 16 + (c ^ csw)];
        float4 k1 = Kf4[(l + 32) * 16 + (c ^ csw)];
#pragma unroll
        for (int r = 0; r < 8; r++) {
            float4 q4 = Qf4[(w * 8 + r) * 16 + c];
            s0[r] += q4.x * k0.x + q4.y * k0.y + q4.z * k0.z + q4.w * k0.w;
            s1[r] += q4.x * k1.x + q4.y * k1.y + q4.z * k1.z + q4.w * k1.w;
        }
    }

    // ---- softmax per row (mask before scale) ----
#pragma unroll
    for (int r = 0; r < 8; r++) {
        int t = w * 8 + r;
        float l0 = (l      <= t) ? s0[r] * 0.125f : NEG8;
        float l1 = (l + 32 <= t) ? s1[r] * 0.125f : NEG8;
        float m = fmaxf(l0, l1);
#pragma unroll
        for (int o = 16; o; o >>= 1) m = fmaxf(m, __shfl_xor_sync(0xffffffffu, m, o));
        float e0 = __expf(l0 - m), e1 = __expf(l1 - m);
        float sum = e0 + e1;
#pragma unroll
        for (int o = 16; o; o >>= 1) sum += __shfl_xor_sync(0xffffffffu, sum, o);
        float inv = 1.f / sum;
        s0[r] = e0 * inv;
        s1[r] = e1 * inv;
    }

    // ---- write P into this warp's own Q rows (warp-private) ----
    __syncwarp();
#pragma unroll
    for (int r = 0; r < 8; r++) {
        int t = w * 8 + r;
        Qs[t * 64 + l]      = s0[r];
        Qs[t * 64 + l + 32] = s1[r];
    }
    __syncwarp();

    // ---- PV: out[t][l], out[t][l+32] = sum_s P[t][s] * v[s][.] ----
    float a0[8], a1[8];
#pragma unroll
    for (int r = 0; r < 8; r++) { a0[r] = 0.f; a1[r] = 0.f; }
    const float2* Vf2 = (const float2*)Vs;
#pragma unroll
    for (int s4 = 0; s4 < 16; s4++) {
        float2 v0 = Vf2[(s4 * 4 + 0) * 32 + l];
        float2 v1 = Vf2[(s4 * 4 + 1) * 32 + l];
        float2 v2 = Vf2[(s4 * 4 + 2) * 32 + l];
        float2 v3 = Vf2[(s4 * 4 + 3) * 32 + l];
#pragma unroll
        for (int r = 0; r < 8; r++) {
            float4 p4 = Qf4[(w * 8 + r) * 16 + s4];
            a0[r] += p4.x * v0.x + p4.y * v1.x + p4.z * v2.x + p4.w * v3.x;
            a1[r] += p4.x * v0.y + p4.y * v1.y + p4.z * v2.y + p4.w * v3.y;
        }
    }

    // ---- store bf16 hi/lo ----
#pragma unroll
    for (int r = 0; r < 8; r++) {
        int t = w * 8 + r;
        size_t ooff = base + (size_t)t * tstride;
        __nv_bfloat16 h0 = __float2bfloat16_rn(a0[r]);
        __nv_bfloat16 h1 = __float2bfloat16_rn(a1[r]);
        oh[ooff + l]      = h0;
        oh[ooff + l + 32] = h1;
        ol[ooff + l]      = __float2bfloat16_rn(a0[r] - __bfloat162float(h0));
        ol[ooff + l + 32] = __float2bfloat16_rn(a1[r] - __bfloat162float(h1));
    }
}

// ---------------------------------------------------------------------------
// out = LayerNorm(a + b); optional bf16 hi/lo split. One warp per row.
// ---------------------------------------------------------------------------
__global__ __launch_bounds__(256)
void add_ln(const float* __restrict__ a, const float* __restrict__ b,
            float* __restrict__ out,
            __nv_bfloat162* __restrict__ oh, __nv_bfloat162* __restrict__ ol)
{
    int row = blockIdx.x * 8 + (threadIdx.x >> 5);
    int l = threadIdx.x & 31;
    const float4* pa = (const float4*)(a + (size_t)row * 512);
    const float4* pb = (const float4*)(b + (size_t)row * 512);

    float4 x[4];
    float s = 0.f;
#pragma unroll
    for (int i = 0; i < 4; i++) {
        float4 u = pa[l + i * 32], w = pb[l + i * 32];
        x[i] = make_float4(u.x + w.x, u.y + w.y, u.z + w.z, u.w + w.w);
        s += x[i].x + x[i].y + x[i].z + x[i].w;
    }
#pragma unroll
    for (int o = 16; o; o >>= 1) s += __shfl_xor_sync(0xffffffffu, s, o);
    float mean = s * (1.f / 512.f);

    float vs = 0.f;
#pragma unroll
    for (int i = 0; i < 4; i++) {
        float dx = x[i].x - mean, dy = x[i].y - mean, dz = x[i].z - mean, dw = x[i].w - mean;
        vs += dx * dx + dy * dy + dz * dz + dw * dw;
    }
#pragma unroll
    for (int o = 16; o; o >>= 1) vs += __shfl_xor_sync(0xffffffffu, vs, o);
    float invstd = rsqrtf(vs * (1.f / 512.f) + 1e-5f);

    float4* po = (float4*)(out + (size_t)row * 512);
#pragma unroll
    for (int i = 0; i < 4; i++) {
        float y0 = (x[i].x - mean) * invstd, y1 = (x[i].y - mean) * invstd;
        float y2 = (x[i].z - mean) * invstd, y3 = (x[i].w - mean) * invstd;
        int fi = row * 128 + l + i * 32;
        po[l + i * 32] = make_float4(y0, y1, y2, y3);
        if (oh) {
            __nv_bfloat162 h0, l0, h1, l1;
            split2(y0, y1, h0, l0);
            split2(y2, y3, h1, l1);
            oh[2 * fi] = h0; oh[2 * fi + 1] = h1;
            ol[2 * fi] = l0; ol[2 * fi + 1] = l1;
        }
    }
}

// ---------------------------------------------------------------------------
// Launch pipeline (graph-capturable: launches only)
// ---------------------------------------------------------------------------
extern "C" void kernel_launch(void* const* d_in, const int* in_sizes, int n_in,
                              void* d_out, int out_size)
{
    const float* xl = (const float*)d_in[0];
    const float* xh = (const float*)d_in[1];
    const float* te = (const float*)d_in[2];
    const float* Wq = (const float*)d_in[3];
    const float* bq = (const float*)d_in[4];
    const float* Wk = (const float*)d_in[5];
    const float* bk = (const float*)d_in[6];
    const float* Wv = (const float*)d_in[7];
    const float* bv = (const float*)d_in[8];
    const float* Wo = (const float*)d_in[9];
    const float* bo = (const float*)d_in[10];
    const float* W1 = (const float*)d_in[11];
    const float* b1 = (const float*)d_in[12];
    const float* W2 = (const float*)d_in[13];
    const float* b2 = (const float*)d_in[14];
    float* out = (float*)d_out;

    float *s0, *s2, *s3, *s4;
    __nv_bfloat16 *bf, *wh, *wl;
    cudaGetSymbolAddress((void**)&s0, g_s0);
    cudaGetSymbolAddress((void**)&s2, g_s2);
    cudaGetSymbolAddress((void**)&s3, g_s3);
    cudaGetSymbolAddress((void**)&s4, g_s4);
    cudaGetSymbolAddress((void**)&bf, g_bf);
    cudaGetSymbolAddress((void**)&wh, g_wh);
    cudaGetSymbolAddress((void**)&wl, g_wl);

    __nv_bfloat16* s0h = bf + 0ull * ELEMS;
    __nv_bfloat16* s0l = bf + 1ull * ELEMS;
    __nv_bfloat16* s1h = bf + 2ull * ELEMS;
    __nv_bfloat16* s1l = bf + 3ull * ELEMS;
    __nv_bfloat16* aoh = bf + 4ull * ELEMS;
    __nv_bfloat16* aol = bf + 5ull * ELEMS;
    __nv_bfloat16* vh  = bf + 6ull * ELEMS;
    __nv_bfloat16* vl  = bf + 7ull * ELEMS;
    __nv_bfloat16* f1h = bf + 8ull * ELEMS;
    __nv_bfloat16* f1l = bf + 9ull * ELEMS;

    cudaFuncSetAttribute(gemm_bf3, cudaFuncAttributeMaxDynamicSharedMemorySize, 65536);

    const dim3 gg(4, 1024);
    const dim3 gkv(8, 1024);           // fused K+V
    const int nadd = ELEMS / 4 / 256;

    // 0: weights transpose + split
    prep_w<<<dim3(16, 16, 6), dim3(32, 8)>>>(Wq, Wk, Wv, Wo, W1, W2, wh, wl);
    // 1: fused residual adds + splits
    add_te01<<<nadd, 256>>>((const float4*)xl, (const float4*)xh, (const float4*)te,
                            (float4*)s0,
                            (__nv_bfloat162*)s0h, (__nv_bfloat162*)s0l,
                            (__nv_bfloat162*)s1h, (__nv_bfloat162*)s1l);
    // 2: Q projection
    gemm_bf3<<<gg, 128, 65536>>>(s0h, s0l, wh + 0 * WSZ, wl + 0 * WSZ, bq, s2,
                                 0, 0, 0, 0, 0, 0, 0, 0);
    // 3: fused K+V projection (K -> s3, V -> s4, both relu)
    gemm_bf3<<<gkv, 128, 65536>>>(s1h, s1l, wh + 1 * WSZ, wl + 1 * WSZ, bk, s3,
                                  0, 0, 1,
                                  wh + 2 * WSZ, wl + 2 * WSZ, bv, s4, 1);
    // 4: attention (profiler target)
    attn64<<<B_ * N_ * H_, 256>>>(s2, s3, s4, aoh, aol);
    // 5: Wo projection
    gemm_bf3<<<gg, 128, 65536>>>(aoh, aol, wh + 3 * WSZ, wl + 3 * WSZ, bo, s3,
                                 0, 0, 0, 0, 0, 0, 0, 0);
    // 6: val = LN(o + s0)
    add_ln<<<TOKENS / 8, 256>>>(s3, s0, s4, (__nv_bfloat162*)vh, (__nv_bfloat162*)vl);
    // 7: ff1 = relu(val @ W1 + b1)
    gemm_bf3<<<gg, 128, 65536>>>(vh, vl, wh + 4 * WSZ, wl + 4 * WSZ, b1, 0,
                                 f1h, f1l, 1, 0, 0, 0, 0, 0);
    // 8: ff2 = ff1 @ W2 + b2 -> s2
    gemm_bf3<<<gg, 128, 65536>>>(f1h, f1l, wh + 5 * WSZ, wl + 5 * WSZ, b2, s2,
                                 0, 0, 0, 0, 0, 0, 0, 0);
    // 9: out = LN(ff2 + val)
    add_ln<<<TOKENS / 8, 256>>>(s2, s4, out, 0, 0);
}